// round 2
// baseline (speedup 1.0000x reference)
#include <cuda_runtime.h>
#include <cstdio>

#define Nn   50000
#define Ee   800000
#define INF_ 500
#define HIDF 128
#define KK   10     // K (polynomial order); K+1 = 11 coefficients

// ------------------------- device scratch (static, no allocs) ---------------
__device__ int   g_deg[Nn];
__device__ int   g_cur[Nn];
__device__ int   g_off[Nn + 1];
__device__ float g_dinv[Nn];
__device__ int   g_src[Ee];
__device__ float g_w[Ee];
__device__ float g_P[KK + 1][(size_t)Nn * HIDF];   // Krylov basis p_j = A^j h  (~282 MB)
__device__ float g_accL[(size_t)Nn * HIDF];
__device__ float g_accH[(size_t)Nn * HIDF];
__device__ float g_sum[4 * HIDF];                  // sumL, sqL, sumH, sqH
__device__ float g_cL[KK + 1];
__device__ float g_cH[KK + 1];
__device__ float g_alpha[2 * HIDF];                // per-branch BN scale  (L then H)
__device__ float g_beta[2 * HIDF];                 // per-branch BN shift

// ------------------------------- small kernels -------------------------------
__global__ void k_init() {
    int i = blockIdx.x * blockDim.x + threadIdx.x;
    if (i < Nn) { g_deg[i] = 0; g_cur[i] = 0; }
    if (i < 4 * HIDF) g_sum[i] = 0.f;
}

__global__ void k_deg(const int* __restrict__ dst) {
    int e = blockIdx.x * blockDim.x + threadIdx.x;
    if (e < Ee) atomicAdd(&g_deg[dst[e]], 1);
}

__global__ void k_dinv() {
    int i = blockIdx.x * blockDim.x + threadIdx.x;
    if (i < Nn) g_dinv[i] = rsqrtf(fmaxf((float)g_deg[i], 1.f));
}

// single-block exclusive scan of g_deg -> g_off (g_off[Nn] = E)
__global__ void k_scan() {
    __shared__ int sh[256];
    __shared__ int carry;
    int tid = threadIdx.x;
    if (tid == 0) carry = 0;
    __syncthreads();
    for (int base = 0; base < Nn; base += 256) {
        int v = (base + tid < Nn) ? g_deg[base + tid] : 0;
        sh[tid] = v;
        __syncthreads();
        for (int off = 1; off < 256; off <<= 1) {
            int t = (tid >= off) ? sh[tid - off] : 0;
            __syncthreads();
            sh[tid] += t;
            __syncthreads();
        }
        if (base + tid < Nn) g_off[base + tid] = carry + sh[tid] - v;
        __syncthreads();
        if (tid == 255) carry += sh[255];
        __syncthreads();
    }
    if (tid == 0) g_off[Nn] = carry;
}

__global__ void k_scatter(const int* __restrict__ src, const int* __restrict__ dst) {
    int e = blockIdx.x * blockDim.x + threadIdx.x;
    if (e < Ee) {
        int s = src[e], d = dst[e];
        int p = atomicAdd(&g_cur[d], 1);
        int idx = g_off[d] + p;
        g_src[idx] = s;
        g_w[idx]   = g_dinv[s] * g_dinv[d];
    }
}

// c_L[j] = gamma_L[j];  c_H[j] = (-1)^j * sum_{k>=j} gamma_H[k] * C(k,j)
__global__ void k_coeff(const float* __restrict__ gL, const float* __restrict__ gH) {
    if (threadIdx.x == 0 && blockIdx.x == 0) {
        double C[KK + 1][KK + 1];
        for (int k = 0; k <= KK; k++)
            for (int j = 0; j <= KK; j++) C[k][j] = 0.0;
        for (int k = 0; k <= KK; k++) {
            C[k][0] = 1.0; C[k][k] = 1.0;
            for (int j = 1; j < k; j++) C[k][j] = C[k - 1][j - 1] + C[k - 1][j];
        }
        for (int j = 0; j <= KK; j++) {
            double s = 0.0;
            for (int k = j; k <= KK; k++) s += (double)gH[k] * C[k][j];
            g_cH[j] = (j & 1) ? (float)(-s) : (float)s;
            g_cL[j] = gL[j];
        }
    }
}

// --------------------------- tiled fp32 GEMM ---------------------------------
// C[M,128] = op(A[M,KDIM]) @ B[KDIM,128] + bias ; optional per-col affine on A,
// optional relu. BM=64, BN=128, BK=16, 256 threads, 4x8 micro-tile.
template <int KDIM, bool AFFINE, bool RELU>
__global__ __launch_bounds__(256)
void k_gemm(const float* __restrict__ A, const float* __restrict__ B,
            const float* __restrict__ bias,
            const float* __restrict__ alpha, const float* __restrict__ beta,
            float* __restrict__ C, int M) {
    __shared__ float As[64][17];
    __shared__ float Bs[16][132];
    int tid = threadIdx.x;
    int tx = tid & 15, ty = tid >> 4;
    int row0 = blockIdx.x * 64;
    float acc[4][8];
#pragma unroll
    for (int i = 0; i < 4; i++)
#pragma unroll
        for (int j = 0; j < 8; j++) acc[i][j] = 0.f;

    for (int k0 = 0; k0 < KDIM; k0 += 16) {
#pragma unroll
        for (int i = tid; i < 64 * 16; i += 256) {
            int r = i >> 4, c = i & 15;
            int gr = row0 + r, gc = k0 + c;
            float v = 0.f;
            if (gr < M && gc < KDIM) {
                v = A[(size_t)gr * KDIM + gc];
                if (AFFINE) v = fmaf(v, alpha[gc], beta[gc]);
            }
            As[r][c] = v;
        }
#pragma unroll
        for (int i = tid; i < 16 * 128; i += 256) {
            int r = i >> 7, c = i & 127;
            int gk = k0 + r;
            Bs[r][c] = (gk < KDIM) ? B[(size_t)gk * 128 + c] : 0.f;
        }
        __syncthreads();
#pragma unroll
        for (int k = 0; k < 16; k++) {
            float4 b0 = *(const float4*)&Bs[k][tx * 8];
            float4 b1 = *(const float4*)&Bs[k][tx * 8 + 4];
#pragma unroll
            for (int i = 0; i < 4; i++) {
                float a = As[ty * 4 + i][k];
                acc[i][0] = fmaf(a, b0.x, acc[i][0]);
                acc[i][1] = fmaf(a, b0.y, acc[i][1]);
                acc[i][2] = fmaf(a, b0.z, acc[i][2]);
                acc[i][3] = fmaf(a, b0.w, acc[i][3]);
                acc[i][4] = fmaf(a, b1.x, acc[i][4]);
                acc[i][5] = fmaf(a, b1.y, acc[i][5]);
                acc[i][6] = fmaf(a, b1.z, acc[i][6]);
                acc[i][7] = fmaf(a, b1.w, acc[i][7]);
            }
        }
        __syncthreads();
    }
#pragma unroll
    for (int i = 0; i < 4; i++) {
        int gr = row0 + ty * 4 + i;
        if (gr < M) {
#pragma unroll
            for (int j = 0; j < 8; j++) {
                int gc = tx * 8 + j;
                float v = acc[i][j] + bias[gc];
                if (RELU) v = fmaxf(v, 0.f);
                C[(size_t)gr * 128 + gc] = v;
            }
        }
    }
}

// --------------------------- sparse propagation ------------------------------
// one warp per dst node; each lane owns a float4 (4 features). p_j = A p_{j-1}.
__global__ __launch_bounds__(256)
void k_prop(int j) {
    int node = blockIdx.x * 8 + (threadIdx.x >> 5);
    if (node >= Nn) return;
    int lane = threadIdx.x & 31;
    const float4* __restrict__ tin = (const float4*)g_P[j - 1];
    float4* __restrict__ tout = (float4*)g_P[j];
    int beg = g_off[node], end = g_off[node + 1];
    float sx = 0.f, sy = 0.f, sz = 0.f, sw = 0.f;
    int e = beg;
    for (; e + 1 < end; e += 2) {
        int   s0 = g_src[e],     s1 = g_src[e + 1];
        float w0 = g_w[e],       w1 = g_w[e + 1];
        float4 v0 = tin[s0 * 32 + lane];
        float4 v1 = tin[s1 * 32 + lane];
        sx = fmaf(w0, v0.x, sx); sy = fmaf(w0, v0.y, sy);
        sz = fmaf(w0, v0.z, sz); sw = fmaf(w0, v0.w, sw);
        sx = fmaf(w1, v1.x, sx); sy = fmaf(w1, v1.y, sy);
        sz = fmaf(w1, v1.z, sz); sw = fmaf(w1, v1.w, sw);
    }
    if (e < end) {
        int s0 = g_src[e]; float w0 = g_w[e];
        float4 v0 = tin[s0 * 32 + lane];
        sx = fmaf(w0, v0.x, sx); sy = fmaf(w0, v0.y, sy);
        sz = fmaf(w0, v0.z, sz); sw = fmaf(w0, v0.w, sw);
    }
    tout[node * 32 + lane] = make_float4(sx, sy, sz, sw);
}

// --------------------------- combine + BN partials ---------------------------
// acc_L = sum_j cL[j] p_j ; acc_H = sum_j cH[j] p_j ; fused per-feature
// sum/sumsq partials for BatchNorm (block-reduced, then atomics).
__global__ __launch_bounds__(256)
void k_combine() {
    int tid = threadIdx.x;
    int fq = tid & 31;         // feature quad: features 4*fq .. 4*fq+3
    int wid = tid >> 5;
    float cl[KK + 1], ch[KK + 1];
#pragma unroll
    for (int j = 0; j <= KK; j++) { cl[j] = g_cL[j]; ch[j] = g_cH[j]; }

    float4 psL = {0, 0, 0, 0}, pqL = {0, 0, 0, 0};
    float4 psH = {0, 0, 0, 0}, pqH = {0, 0, 0, 0};

    for (int node = blockIdx.x * 8 + wid; node < Nn; node += gridDim.x * 8) {
        int base = node * 32 + fq;
        float4 aL = {0, 0, 0, 0}, aH = {0, 0, 0, 0};
#pragma unroll
        for (int j = 0; j <= KK; j++) {
            float4 p = ((const float4*)g_P[j])[base];
            aL.x = fmaf(cl[j], p.x, aL.x); aL.y = fmaf(cl[j], p.y, aL.y);
            aL.z = fmaf(cl[j], p.z, aL.z); aL.w = fmaf(cl[j], p.w, aL.w);
            aH.x = fmaf(ch[j], p.x, aH.x); aH.y = fmaf(ch[j], p.y, aH.y);
            aH.z = fmaf(ch[j], p.z, aH.z); aH.w = fmaf(ch[j], p.w, aH.w);
        }
        ((float4*)g_accL)[base] = aL;
        ((float4*)g_accH)[base] = aH;
        psL.x += aL.x; psL.y += aL.y; psL.z += aL.z; psL.w += aL.w;
        pqL.x = fmaf(aL.x, aL.x, pqL.x); pqL.y = fmaf(aL.y, aL.y, pqL.y);
        pqL.z = fmaf(aL.z, aL.z, pqL.z); pqL.w = fmaf(aL.w, aL.w, pqL.w);
        psH.x += aH.x; psH.y += aH.y; psH.z += aH.z; psH.w += aH.w;
        pqH.x = fmaf(aH.x, aH.x, pqH.x); pqH.y = fmaf(aH.y, aH.y, pqH.y);
        pqH.z = fmaf(aH.z, aH.z, pqH.z); pqH.w = fmaf(aH.w, aH.w, pqH.w);
    }

    __shared__ float4 sh[4][256];
    sh[0][tid] = psL; sh[1][tid] = pqL; sh[2][tid] = psH; sh[3][tid] = pqH;
    __syncthreads();
    if (tid < 32) {
        float4 a0 = sh[0][tid], a1 = sh[1][tid], a2 = sh[2][tid], a3 = sh[3][tid];
#pragma unroll
        for (int w = 1; w < 8; w++) {
            float4 t;
            t = sh[0][tid + 32 * w]; a0.x += t.x; a0.y += t.y; a0.z += t.z; a0.w += t.w;
            t = sh[1][tid + 32 * w]; a1.x += t.x; a1.y += t.y; a1.z += t.z; a1.w += t.w;
            t = sh[2][tid + 32 * w]; a2.x += t.x; a2.y += t.y; a2.z += t.z; a2.w += t.w;
            t = sh[3][tid + 32 * w]; a3.x += t.x; a3.y += t.y; a3.z += t.z; a3.w += t.w;
        }
        int f = tid * 4;
        atomicAdd(&g_sum[0 * HIDF + f + 0], a0.x); atomicAdd(&g_sum[0 * HIDF + f + 1], a0.y);
        atomicAdd(&g_sum[0 * HIDF + f + 2], a0.z); atomicAdd(&g_sum[0 * HIDF + f + 3], a0.w);
        atomicAdd(&g_sum[1 * HIDF + f + 0], a1.x); atomicAdd(&g_sum[1 * HIDF + f + 1], a1.y);
        atomicAdd(&g_sum[1 * HIDF + f + 2], a1.z); atomicAdd(&g_sum[1 * HIDF + f + 3], a1.w);
        atomicAdd(&g_sum[2 * HIDF + f + 0], a2.x); atomicAdd(&g_sum[2 * HIDF + f + 1], a2.y);
        atomicAdd(&g_sum[2 * HIDF + f + 2], a2.z); atomicAdd(&g_sum[2 * HIDF + f + 3], a2.w);
        atomicAdd(&g_sum[3 * HIDF + f + 0], a3.x); atomicAdd(&g_sum[3 * HIDF + f + 1], a3.y);
        atomicAdd(&g_sum[3 * HIDF + f + 2], a3.z); atomicAdd(&g_sum[3 * HIDF + f + 3], a3.w);
    }
}

__global__ void k_bnfinal(const float* __restrict__ bn_scale,
                          const float* __restrict__ bn_shift) {
    int f = threadIdx.x;
    if (f < HIDF) {
        const float invN = 1.f / (float)Nn;
        // L branch
        float mu = g_sum[f] * invN;
        float var = g_sum[HIDF + f] * invN - mu * mu;
        float a = rsqrtf(var + 1e-5f) * bn_scale[f];
        g_alpha[f] = a;
        g_beta[f] = bn_shift[f] - mu * a;
        // H branch
        mu = g_sum[2 * HIDF + f] * invN;
        var = g_sum[3 * HIDF + f] * invN - mu * mu;
        a = rsqrtf(var + 1e-5f) * bn_scale[f];
        g_alpha[HIDF + f] = a;
        g_beta[HIDF + f] = bn_shift[f] - mu * a;
    }
}

// ------------------------------- launcher ------------------------------------
extern "C" void kernel_launch(void* const* d_in, const int* in_sizes, int n_in,
                              void* d_out, int out_size) {
    const float* x    = (const float*)d_in[0];
    const int*   ei   = (const int*)d_in[1];
    const float* W_in = (const float*)d_in[2];
    const float* b_in = (const float*)d_in[3];
    const float* gL   = (const float*)d_in[4];
    const float* gH   = (const float*)d_in[5];
    const float* bns  = (const float*)d_in[6];
    const float* bnb  = (const float*)d_in[7];
    const float* W_up = (const float*)d_in[8];
    const float* b_up = (const float*)d_in[9];
    float* out = (float*)d_out;

    const int* src = ei;
    const int* dst = ei + Ee;

    void *pP, *pAL, *pAH, *pAl, *pBe;
    cudaGetSymbolAddress(&pP,  g_P);
    cudaGetSymbolAddress(&pAL, g_accL);
    cudaGetSymbolAddress(&pAH, g_accH);
    cudaGetSymbolAddress(&pAl, g_alpha);
    cudaGetSymbolAddress(&pBe, g_beta);
    float* P0    = (float*)pP;                 // g_P[0]
    float* accL  = (float*)pAL;
    float* accH  = (float*)pAH;
    float* alpha = (float*)pAl;
    float* beta  = (float*)pBe;

    const int nblkN = (Nn + 255) / 256;   // 196
    const int nblkE = (Ee + 255) / 256;   // 3125
    const int gemmB = (Nn + 63) / 64;     // 782

    k_init<<<nblkN, 256>>>();
    k_deg<<<nblkE, 256>>>(dst);
    k_dinv<<<nblkN, 256>>>();
    k_scan<<<1, 256>>>();
    k_scatter<<<nblkE, 256>>>(src, dst);
    k_coeff<<<1, 32>>>(gL, gH);

    // p_0 = h = x @ W_in + b_in
    k_gemm<INF_, false, false><<<gemmB, 256>>>(x, W_in, b_in, nullptr, nullptr, P0, Nn);

    // Krylov chain p_j = A p_{j-1}
    for (int j = 1; j <= KK; j++)
        k_prop<<<(Nn + 7) / 8, 256>>>(j);

    // acc_L / acc_H + BN statistics
    k_combine<<<296, 256>>>();
    k_bnfinal<<<1, 128>>>(bns, bnb);

    // Z = relu(BN(acc) @ W_up + b_up) for both branches
    k_gemm<HIDF, true, true><<<gemmB, 256>>>(accL, W_up, b_up, alpha, beta,
                                             out, Nn);
    k_gemm<HIDF, true, true><<<gemmB, 256>>>(accH, W_up, b_up, alpha + HIDF, beta + HIDF,
                                             out + (size_t)Nn * HIDF, Nn);
}

// round 3
// speedup vs baseline: 1.2122x; 1.2122x over previous
#include <cuda_runtime.h>
#include <cstdio>

#define Nn   50000
#define Ee   800000
#define INF_ 500
#define HIDF 128
#define KK   10     // K (polynomial order); K+1 = 11 coefficients

// ------------------------- device scratch (static, no allocs) ---------------
__device__ int   g_deg[Nn];
__device__ int   g_cur[Nn];
__device__ int   g_off[Nn + 1];
__device__ float g_dinv[Nn];
__device__ int2  g_sw[Ee];                         // packed {src, __float_as_int(w)}
__device__ int   g_bsum[256];
__device__ int   g_boff[256];
__device__ float g_P[KK + 1][(size_t)Nn * HIDF];   // Krylov basis p_j = A^j h  (~282 MB)
__device__ float g_accL[(size_t)Nn * HIDF];
__device__ float g_accH[(size_t)Nn * HIDF];
__device__ float g_sum[4 * HIDF];                  // sumL, sqL, sumH, sqH
__device__ float g_cL[KK + 1];
__device__ float g_cH[KK + 1];
__device__ float g_alpha[2 * HIDF];                // per-branch BN scale  (L then H)
__device__ float g_beta[2 * HIDF];                 // per-branch BN shift

// ------------------------- f32x2 packed-FMA helpers --------------------------
__device__ __forceinline__ unsigned long long pack2(float lo, float hi) {
    unsigned long long r;
    asm("mov.b64 %0, {%1, %2};" : "=l"(r) : "f"(lo), "f"(hi));
    return r;
}
__device__ __forceinline__ void unpack2(unsigned long long p, float& lo, float& hi) {
    asm("mov.b64 {%0, %1}, %2;" : "=f"(lo), "=f"(hi) : "l"(p));
}
#define FMA2(d, a, b, c) \
    asm("fma.rn.f32x2 %0, %1, %2, %3;" : "=l"(d) : "l"(a), "l"(b), "l"(c))

// ------------------------------- small kernels -------------------------------
__global__ void k_init() {
    int i = blockIdx.x * blockDim.x + threadIdx.x;
    if (i < Nn) { g_deg[i] = 0; g_cur[i] = 0; }
    if (i < 4 * HIDF) g_sum[i] = 0.f;
    if (i == 0) g_off[Nn] = Ee;
}

__global__ void k_deg(const int* __restrict__ dst) {
    int e = blockIdx.x * blockDim.x + threadIdx.x;
    if (e < Ee) atomicAdd(&g_deg[dst[e]], 1);
}

__global__ void k_dinv() {
    int i = blockIdx.x * blockDim.x + threadIdx.x;
    if (i < Nn) g_dinv[i] = rsqrtf(fmaxf((float)g_deg[i], 1.f));
}

// ------------- multi-block exclusive scan of g_deg -> g_off ------------------
__global__ void k_blocksum() {
    int i = blockIdx.x * 256 + threadIdx.x;
    int v = (i < Nn) ? g_deg[i] : 0;
#pragma unroll
    for (int o = 16; o; o >>= 1) v += __shfl_down_sync(~0u, v, o);
    __shared__ int ws[8];
    if ((threadIdx.x & 31) == 0) ws[threadIdx.x >> 5] = v;
    __syncthreads();
    if (threadIdx.x < 8) {
        int t = ws[threadIdx.x];
#pragma unroll
        for (int o = 4; o; o >>= 1) t += __shfl_down_sync(0xff, t, o);
        if (threadIdx.x == 0) g_bsum[blockIdx.x] = t;
    }
}

__global__ void k_scanb(int nb) {   // single block, 256 threads; exclusive scan of block sums
    int t = threadIdx.x;
    int lane = t & 31, wid = t >> 5;
    int v = (t < nb) ? g_bsum[t] : 0;
    int s = v;
#pragma unroll
    for (int o = 1; o < 32; o <<= 1) {
        int u = __shfl_up_sync(~0u, s, o);
        if (lane >= o) s += u;
    }
    __shared__ int ws[8];
    if (lane == 31) ws[wid] = s;
    __syncthreads();
    if (t < 8) {
        int u = ws[t];
#pragma unroll
        for (int o = 1; o < 8; o <<= 1) {
            int q = __shfl_up_sync(0xff, u, o);
            if (t >= o) u += q;
        }
        ws[t] = u;
    }
    __syncthreads();
    int excl = s - v + (wid ? ws[wid - 1] : 0);
    if (t < nb) g_boff[t] = excl;
}

__global__ void k_scanwrite() {
    int i = blockIdx.x * 256 + threadIdx.x;
    int lane = threadIdx.x & 31, wid = threadIdx.x >> 5;
    int v = (i < Nn) ? g_deg[i] : 0;
    int s = v;
#pragma unroll
    for (int o = 1; o < 32; o <<= 1) {
        int u = __shfl_up_sync(~0u, s, o);
        if (lane >= o) s += u;
    }
    __shared__ int ws[8];
    if (lane == 31) ws[wid] = s;
    __syncthreads();
    if (threadIdx.x < 8) {
        int u = ws[threadIdx.x];
#pragma unroll
        for (int o = 1; o < 8; o <<= 1) {
            int q = __shfl_up_sync(0xff, u, o);
            if (threadIdx.x >= o) u += q;
        }
        ws[threadIdx.x] = u;
    }
    __syncthreads();
    int excl = s - v + (wid ? ws[wid - 1] : 0);
    if (i < Nn) g_off[i] = g_boff[blockIdx.x] + excl;
}

__global__ void k_scatter(const int* __restrict__ src, const int* __restrict__ dst) {
    int e = blockIdx.x * blockDim.x + threadIdx.x;
    if (e < Ee) {
        int s = src[e], d = dst[e];
        int p = atomicAdd(&g_cur[d], 1);
        int idx = g_off[d] + p;
        float w = g_dinv[s] * g_dinv[d];
        g_sw[idx] = make_int2(s, __float_as_int(w));
    }
}

// c_L[j] = gamma_L[j];  c_H[j] = (-1)^j * sum_{k>=j} gamma_H[k] * C(k,j)
__global__ void k_coeff(const float* __restrict__ gL, const float* __restrict__ gH) {
    if (threadIdx.x == 0 && blockIdx.x == 0) {
        double C[KK + 1][KK + 1];
        for (int k = 0; k <= KK; k++)
            for (int j = 0; j <= KK; j++) C[k][j] = 0.0;
        for (int k = 0; k <= KK; k++) {
            C[k][0] = 1.0; C[k][k] = 1.0;
            for (int j = 1; j < k; j++) C[k][j] = C[k - 1][j - 1] + C[k - 1][j];
        }
        for (int j = 0; j <= KK; j++) {
            double s = 0.0;
            for (int k = j; k <= KK; k++) s += (double)gH[k] * C[k][j];
            g_cH[j] = (j & 1) ? (float)(-s) : (float)s;
            g_cL[j] = gL[j];
        }
    }
}

// --------------------------- tiled fp32 GEMM (f32x2 inner) -------------------
// C[M,128] = A[M,KDIM] @ B[KDIM,128] + bias. BM=64, BN=128, BK=16,
// 256 threads, 4x8 micro-tile, packed fma.rn.f32x2 accumulation.
template <int KDIM>
__global__ __launch_bounds__(256)
void k_gemm1(const float* __restrict__ A, const float* __restrict__ B,
             const float* __restrict__ bias, float* __restrict__ C, int M) {
    __shared__ __align__(16) float As[64][17];
    __shared__ __align__(16) float Bs[16][132];
    int tid = threadIdx.x;
    int tx = tid & 15, ty = tid >> 4;
    int row0 = blockIdx.x * 64;
    unsigned long long acc2[4][4];
#pragma unroll
    for (int i = 0; i < 4; i++)
#pragma unroll
        for (int j = 0; j < 4; j++) acc2[i][j] = 0ull;

    for (int k0 = 0; k0 < KDIM; k0 += 16) {
#pragma unroll
        for (int i = tid; i < 64 * 16; i += 256) {
            int r = i >> 4, c = i & 15;
            int gr = row0 + r, gc = k0 + c;
            As[r][c] = (gr < M && gc < KDIM) ? A[(size_t)gr * KDIM + gc] : 0.f;
        }
#pragma unroll
        for (int i = tid; i < 16 * 128; i += 256) {
            int r = i >> 7, c = i & 127;
            int gk = k0 + r;
            Bs[r][c] = (gk < KDIM) ? B[(size_t)gk * 128 + c] : 0.f;
        }
        __syncthreads();
#pragma unroll
        for (int k = 0; k < 16; k++) {
            const ulonglong2* brow = (const ulonglong2*)&Bs[k][tx * 8];
            ulonglong2 q0 = brow[0];   // (b0,b1) (b2,b3)
            ulonglong2 q1 = brow[1];   // (b4,b5) (b6,b7)
#pragma unroll
            for (int i = 0; i < 4; i++) {
                float a = As[ty * 4 + i][k];
                unsigned long long aa = pack2(a, a);
                FMA2(acc2[i][0], aa, q0.x, acc2[i][0]);
                FMA2(acc2[i][1], aa, q0.y, acc2[i][1]);
                FMA2(acc2[i][2], aa, q1.x, acc2[i][2]);
                FMA2(acc2[i][3], aa, q1.y, acc2[i][3]);
            }
        }
        __syncthreads();
    }
#pragma unroll
    for (int i = 0; i < 4; i++) {
        int gr = row0 + ty * 4 + i;
        if (gr < M) {
#pragma unroll
            for (int j = 0; j < 4; j++) {
                float lo, hi;
                unpack2(acc2[i][j], lo, hi);
                int gc = tx * 8 + 2 * j;
                C[(size_t)gr * 128 + gc]     = lo + bias[gc];
                C[(size_t)gr * 128 + gc + 1] = hi + bias[gc + 1];
            }
        }
    }
}

// Epilogue GEMM: both branches in one launch (blockIdx.y = branch).
// C = relu((A*alpha + beta) @ W_up + b_up), K = 128.
__global__ __launch_bounds__(256)
void k_gemm_ep(const float* __restrict__ AL, const float* __restrict__ AH,
               const float* __restrict__ B, const float* __restrict__ bias,
               float* __restrict__ out, int M) {
    __shared__ __align__(16) float As[64][17];
    __shared__ __align__(16) float Bs[16][132];
    int br = blockIdx.y;
    const float* A = br ? AH : AL;
    const float* alpha = g_alpha + br * HIDF;
    const float* beta  = g_beta  + br * HIDF;
    float* C = out + (size_t)br * Nn * HIDF;

    int tid = threadIdx.x;
    int tx = tid & 15, ty = tid >> 4;
    int row0 = blockIdx.x * 64;
    unsigned long long acc2[4][4];
#pragma unroll
    for (int i = 0; i < 4; i++)
#pragma unroll
        for (int j = 0; j < 4; j++) acc2[i][j] = 0ull;

    for (int k0 = 0; k0 < HIDF; k0 += 16) {
#pragma unroll
        for (int i = tid; i < 64 * 16; i += 256) {
            int r = i >> 4, c = i & 15;
            int gr = row0 + r, gc = k0 + c;
            float v = 0.f;
            if (gr < M) v = fmaf(A[(size_t)gr * HIDF + gc], alpha[gc], beta[gc]);
            As[r][c] = v;
        }
#pragma unroll
        for (int i = tid; i < 16 * 128; i += 256) {
            int r = i >> 7, c = i & 127;
            Bs[r][c] = B[(size_t)(k0 + r) * 128 + c];
        }
        __syncthreads();
#pragma unroll
        for (int k = 0; k < 16; k++) {
            const ulonglong2* brow = (const ulonglong2*)&Bs[k][tx * 8];
            ulonglong2 q0 = brow[0];
            ulonglong2 q1 = brow[1];
#pragma unroll
            for (int i = 0; i < 4; i++) {
                float a = As[ty * 4 + i][k];
                unsigned long long aa = pack2(a, a);
                FMA2(acc2[i][0], aa, q0.x, acc2[i][0]);
                FMA2(acc2[i][1], aa, q0.y, acc2[i][1]);
                FMA2(acc2[i][2], aa, q1.x, acc2[i][2]);
                FMA2(acc2[i][3], aa, q1.y, acc2[i][3]);
            }
        }
        __syncthreads();
    }
#pragma unroll
    for (int i = 0; i < 4; i++) {
        int gr = row0 + ty * 4 + i;
        if (gr < M) {
#pragma unroll
            for (int j = 0; j < 4; j++) {
                float lo, hi;
                unpack2(acc2[i][j], lo, hi);
                int gc = tx * 8 + 2 * j;
                C[(size_t)gr * 128 + gc]     = fmaxf(lo + bias[gc], 0.f);
                C[(size_t)gr * 128 + gc + 1] = fmaxf(hi + bias[gc + 1], 0.f);
            }
        }
    }
}

// --------------------------- sparse propagation ------------------------------
// one warp per dst node; each lane owns a float4 (4 features). p_j = A p_{j-1}.
__global__ __launch_bounds__(256)
void k_prop(int j) {
    int node = blockIdx.x * 8 + (threadIdx.x >> 5);
    if (node >= Nn) return;
    int lane = threadIdx.x & 31;
    const float4* __restrict__ tin = (const float4*)g_P[j - 1];
    float4* __restrict__ tout = (float4*)g_P[j];
    int beg = g_off[node], end = g_off[node + 1];
    float sx = 0.f, sy = 0.f, sz = 0.f, sw = 0.f;
    int e = beg;
    for (; e + 4 <= end; e += 4) {
        int2 a0 = g_sw[e],     a1 = g_sw[e + 1];
        int2 a2 = g_sw[e + 2], a3 = g_sw[e + 3];
        float4 v0 = __ldg(&tin[a0.x * 32 + lane]);
        float4 v1 = __ldg(&tin[a1.x * 32 + lane]);
        float4 v2 = __ldg(&tin[a2.x * 32 + lane]);
        float4 v3 = __ldg(&tin[a3.x * 32 + lane]);
        float w0 = __int_as_float(a0.y), w1 = __int_as_float(a1.y);
        float w2 = __int_as_float(a2.y), w3 = __int_as_float(a3.y);
        sx = fmaf(w0, v0.x, sx); sy = fmaf(w0, v0.y, sy);
        sz = fmaf(w0, v0.z, sz); sw = fmaf(w0, v0.w, sw);
        sx = fmaf(w1, v1.x, sx); sy = fmaf(w1, v1.y, sy);
        sz = fmaf(w1, v1.z, sz); sw = fmaf(w1, v1.w, sw);
        sx = fmaf(w2, v2.x, sx); sy = fmaf(w2, v2.y, sy);
        sz = fmaf(w2, v2.z, sz); sw = fmaf(w2, v2.w, sw);
        sx = fmaf(w3, v3.x, sx); sy = fmaf(w3, v3.y, sy);
        sz = fmaf(w3, v3.z, sz); sw = fmaf(w3, v3.w, sw);
    }
    for (; e < end; e++) {
        int2 a0 = g_sw[e];
        float w0 = __int_as_float(a0.y);
        float4 v0 = __ldg(&tin[a0.x * 32 + lane]);
        sx = fmaf(w0, v0.x, sx); sy = fmaf(w0, v0.y, sy);
        sz = fmaf(w0, v0.z, sz); sw = fmaf(w0, v0.w, sw);
    }
    tout[node * 32 + lane] = make_float4(sx, sy, sz, sw);
}

// --------------------------- combine + BN partials ---------------------------
__global__ __launch_bounds__(256)
void k_combine() {
    int tid = threadIdx.x;
    int fq = tid & 31;         // feature quad: features 4*fq .. 4*fq+3
    int wid = tid >> 5;
    float cl[KK + 1], ch[KK + 1];
#pragma unroll
    for (int j = 0; j <= KK; j++) { cl[j] = g_cL[j]; ch[j] = g_cH[j]; }

    float4 psL = {0, 0, 0, 0}, pqL = {0, 0, 0, 0};
    float4 psH = {0, 0, 0, 0}, pqH = {0, 0, 0, 0};

    for (int node = blockIdx.x * 8 + wid; node < Nn; node += gridDim.x * 8) {
        int base = node * 32 + fq;
        float4 aL = {0, 0, 0, 0}, aH = {0, 0, 0, 0};
#pragma unroll
        for (int j = 0; j <= KK; j++) {
            float4 p = ((const float4*)g_P[j])[base];
            aL.x = fmaf(cl[j], p.x, aL.x); aL.y = fmaf(cl[j], p.y, aL.y);
            aL.z = fmaf(cl[j], p.z, aL.z); aL.w = fmaf(cl[j], p.w, aL.w);
            aH.x = fmaf(ch[j], p.x, aH.x); aH.y = fmaf(ch[j], p.y, aH.y);
            aH.z = fmaf(ch[j], p.z, aH.z); aH.w = fmaf(ch[j], p.w, aH.w);
        }
        ((float4*)g_accL)[base] = aL;
        ((float4*)g_accH)[base] = aH;
        psL.x += aL.x; psL.y += aL.y; psL.z += aL.z; psL.w += aL.w;
        pqL.x = fmaf(aL.x, aL.x, pqL.x); pqL.y = fmaf(aL.y, aL.y, pqL.y);
        pqL.z = fmaf(aL.z, aL.z, pqL.z); pqL.w = fmaf(aL.w, aL.w, pqL.w);
        psH.x += aH.x; psH.y += aH.y; psH.z += aH.z; psH.w += aH.w;
        pqH.x = fmaf(aH.x, aH.x, pqH.x); pqH.y = fmaf(aH.y, aH.y, pqH.y);
        pqH.z = fmaf(aH.z, aH.z, pqH.z); pqH.w = fmaf(aH.w, aH.w, pqH.w);
    }

    __shared__ float4 sh[4][256];
    sh[0][tid] = psL; sh[1][tid] = pqL; sh[2][tid] = psH; sh[3][tid] = pqH;
    __syncthreads();
    if (tid < 32) {
        float4 a0 = sh[0][tid], a1 = sh[1][tid], a2 = sh[2][tid], a3 = sh[3][tid];
#pragma unroll
        for (int w = 1; w < 8; w++) {
            float4 t;
            t = sh[0][tid + 32 * w]; a0.x += t.x; a0.y += t.y; a0.z += t.z; a0.w += t.w;
            t = sh[1][tid + 32 * w]; a1.x += t.x; a1.y += t.y; a1.z += t.z; a1.w += t.w;
            t = sh[2][tid + 32 * w]; a2.x += t.x; a2.y += t.y; a2.z += t.z; a2.w += t.w;
            t = sh[3][tid + 32 * w]; a3.x += t.x; a3.y += t.y; a3.z += t.z; a3.w += t.w;
        }
        int f = tid * 4;
        atomicAdd(&g_sum[0 * HIDF + f + 0], a0.x); atomicAdd(&g_sum[0 * HIDF + f + 1], a0.y);
        atomicAdd(&g_sum[0 * HIDF + f + 2], a0.z); atomicAdd(&g_sum[0 * HIDF + f + 3], a0.w);
        atomicAdd(&g_sum[1 * HIDF + f + 0], a1.x); atomicAdd(&g_sum[1 * HIDF + f + 1], a1.y);
        atomicAdd(&g_sum[1 * HIDF + f + 2], a1.z); atomicAdd(&g_sum[1 * HIDF + f + 3], a1.w);
        atomicAdd(&g_sum[2 * HIDF + f + 0], a2.x); atomicAdd(&g_sum[2 * HIDF + f + 1], a2.y);
        atomicAdd(&g_sum[2 * HIDF + f + 2], a2.z); atomicAdd(&g_sum[2 * HIDF + f + 3], a2.w);
        atomicAdd(&g_sum[3 * HIDF + f + 0], a3.x); atomicAdd(&g_sum[3 * HIDF + f + 1], a3.y);
        atomicAdd(&g_sum[3 * HIDF + f + 2], a3.z); atomicAdd(&g_sum[3 * HIDF + f + 3], a3.w);
    }
}

__global__ void k_bnfinal(const float* __restrict__ bn_scale,
                          const float* __restrict__ bn_shift) {
    int f = threadIdx.x;
    if (f < HIDF) {
        const float invN = 1.f / (float)Nn;
        float mu = g_sum[f] * invN;
        float var = g_sum[HIDF + f] * invN - mu * mu;
        float a = rsqrtf(var + 1e-5f) * bn_scale[f];
        g_alpha[f] = a;
        g_beta[f] = bn_shift[f] - mu * a;
        mu = g_sum[2 * HIDF + f] * invN;
        var = g_sum[3 * HIDF + f] * invN - mu * mu;
        a = rsqrtf(var + 1e-5f) * bn_scale[f];
        g_alpha[HIDF + f] = a;
        g_beta[HIDF + f] = bn_shift[f] - mu * a;
    }
}

// ------------------------------- launcher ------------------------------------
extern "C" void kernel_launch(void* const* d_in, const int* in_sizes, int n_in,
                              void* d_out, int out_size) {
    const float* x    = (const float*)d_in[0];
    const int*   ei   = (const int*)d_in[1];
    const float* W_in = (const float*)d_in[2];
    const float* b_in = (const float*)d_in[3];
    const float* gL   = (const float*)d_in[4];
    const float* gH   = (const float*)d_in[5];
    const float* bns  = (const float*)d_in[6];
    const float* bnb  = (const float*)d_in[7];
    const float* W_up = (const float*)d_in[8];
    const float* b_up = (const float*)d_in[9];
    float* out = (float*)d_out;

    const int* src = ei;
    const int* dst = ei + Ee;

    void *pP, *pAL, *pAH;
    cudaGetSymbolAddress(&pP,  g_P);
    cudaGetSymbolAddress(&pAL, g_accL);
    cudaGetSymbolAddress(&pAH, g_accH);
    float* P0   = (float*)pP;                  // g_P[0]
    float* accL = (float*)pAL;
    float* accH = (float*)pAH;

    const int nblkN = (Nn + 255) / 256;   // 196
    const int nblkE = (Ee + 255) / 256;   // 3125
    const int gemmB = (Nn + 63) / 64;     // 782

    k_init<<<nblkN, 256>>>();
    k_deg<<<nblkE, 256>>>(dst);
    k_dinv<<<nblkN, 256>>>();
    k_blocksum<<<nblkN, 256>>>();
    k_scanb<<<1, 256>>>(nblkN);
    k_scanwrite<<<nblkN, 256>>>();
    k_scatter<<<nblkE, 256>>>(src, dst);
    k_coeff<<<1, 32>>>(gL, gH);

    // p_0 = h = x @ W_in + b_in
    k_gemm1<INF_><<<gemmB, 256>>>(x, W_in, b_in, P0, Nn);

    // Krylov chain p_j = A p_{j-1}
    for (int j = 1; j <= KK; j++)
        k_prop<<<(Nn + 7) / 8, 256>>>(j);

    // acc_L / acc_H + BN statistics
    k_combine<<<296, 256>>>();
    k_bnfinal<<<1, 128>>>(bns, bnb);

    // Z = relu(BN(acc) @ W_up + b_up), both branches in one launch
    dim3 epg(gemmB, 2);
    k_gemm_ep<<<epg, 256>>>(accL, accH, W_up, b_up, out, Nn);
}